// round 13
// baseline (speedup 1.0000x reference)
#include <cuda_runtime.h>
#include <cuda.h>
#include <cstdint>

// ============================================================================
// out[m,n] = tanh( sum_k x[m,k] * (exp(s[k]) * V[k,n]) + bias[n] )
// M = 1048576, K = N = 128, fp32 in/out.
//
// sm_103a: persistent warp-specialized tcgen05 TF32 TS-mode GEMM (384 thr):
//   W' = exp(s)*V (tf32, bias-compensated) lives in TMEM (cols 384-511) as
//   the A operand. x tiles stream through a 3-deep smem ring (B operand);
//   ring slots freed by MMA commit (DF). D[n,m] transposed, TRIPLE-buffered
//   in TMEM cols 0-383 -> MMA(u) only needs epi(u-3) drained.
//   Epilogue stores directly: lane = n = contiguous output direction, so
//   STG.32.CS is fully coalesced (no smem bounce); DE signaled right after
//   LDTM drains D into registers.
//   warps 0-7  : epilogue (LDTM x2 + early DE + bias + tanh.approx + STG.CS)
//   warps 8-11 : producers (cp.async.cg, software-pipelined wait_group 1)
//   warp  8    : issues 16x tcgen05.mma.kind::tf32 TS per tile
// compute_103 (portable PTX) stage: smem-tiled FFMA fallback.
// ============================================================================

#if defined(__CUDA_ARCH__) && !defined(__CUDA_ARCH_FEAT_SM103_ALL) && !defined(__CUDA_ARCH_FEAT_SM100_ALL)
#define RWF_NO_TCGEN05 1
#endif

#define NTHREADS 384
#define SMEM_BYTES 199680
#define IDESC_TF32 0x8200910u   // cF32 | aTF32 | bTF32 | N=128 | M=128

// offsets from 1024-aligned smem base (tcgen05 path)
#define OFF_BIAS 128
#define OFF_SEXP 768
#define OFF_A0   2048           // 3 x 64KB x-tile ring
#define A_STRIDE 65536

// mbarrier offsets (from aligned base)
#define MB_AF   0               // 3 x 8B (B tile filled)
#define MB_DF   24              // 3 x 8B (MMA committed; B consumed, D full)
#define MB_DE   48              // 3 x 8B (D drained by epilogue LDTM)
#define MB_TMEM 72

// TMEM column map: D buffers at 128*(u%3), W at 384
#define TM_W  384

// truncation bias compensation: E[trunc rel err] = -2^-11 on B (x, HW-truncated)
#define W_BIAS_COMP 1.00048828125f

// ---------------------------------------------------------------------------
// Generic helpers (portable)
// ---------------------------------------------------------------------------
__device__ __forceinline__ uint32_t smem_u32(const void* p) {
    uint32_t a;
    asm("{ .reg .u64 t; cvta.to.shared.u64 t, %1; cvt.u32.u64 %0, t; }"
        : "=r"(a) : "l"(p));
    return a;
}

__device__ __forceinline__ float tanh_fast(float z) {
    float r;
    asm("tanh.approx.f32 %0, %1;" : "=f"(r) : "f"(z));
    return r;
}

#ifndef RWF_NO_TCGEN05
// ---------------------------------------------------------------------------
// sm_103a-only helpers
// ---------------------------------------------------------------------------
__device__ __forceinline__ uint32_t elect_one() {
    uint32_t r;
    asm volatile("{ .reg .pred p; elect.sync _|p, 0xFFFFFFFF; selp.b32 %0, 1, 0, p; }"
                 : "=r"(r));
    return r;
}

#define MBAR_INIT(addr, cnt) \
    asm volatile("mbarrier.init.shared.b64 [%0], %1;" :: "r"(addr), "r"(cnt) : "memory")

#define MBAR_ARRIVE(addr) \
    asm volatile("mbarrier.arrive.shared.b64 _, [%0];" :: "r"(addr) : "memory")

#define MBAR_WAIT(addr, ph) do {                                              \
    uint32_t _a = (addr), _p = (ph), _d;                                      \
    asm volatile("{\n\t.reg .pred p;\n\t"                                     \
        "mbarrier.try_wait.parity.acquire.cta.shared::cta.b64 p, [%1], %2;\n\t" \
        "selp.b32 %0, 1, 0, p;\n\t}"                                          \
        : "=r"(_d) : "r"(_a), "r"(_p) : "memory");                            \
    while (!_d) {                                                             \
        asm volatile("{\n\t.reg .pred p;\n\t"                                 \
            "mbarrier.try_wait.parity.acquire.cta.shared::cta.b64 p, [%1], %2, 0x989680;\n\t" \
            "selp.b32 %0, 1, 0, p;\n\t}"                                      \
            : "=r"(_d) : "r"(_a), "r"(_p) : "memory");                        \
    }                                                                         \
} while (0)

#define FENCE_ASYNC_SHARED() \
    asm volatile("fence.proxy.async.shared::cta;" ::: "memory")

#define CP_ASYNC16(saddr, gptr) \
    asm volatile("cp.async.cg.shared.global [%0], [%1], 16;" \
                 :: "r"(saddr), "l"(gptr) : "memory")
#define CP_COMMIT() asm volatile("cp.async.commit_group;" ::: "memory")
#define CP_WAIT1()  asm volatile("cp.async.wait_group 1;" ::: "memory")
#define CP_WAIT0()  asm volatile("cp.async.wait_group 0;" ::: "memory")

#define TCG_ALLOC(smem_addr, ncols) \
    asm volatile("tcgen05.alloc.cta_group::1.sync.aligned.shared::cta.b32 [%0], %1;" \
                 :: "r"(smem_addr), "r"(ncols) : "memory")
#define TCG_RELINQ() \
    asm volatile("tcgen05.relinquish_alloc_permit.cta_group::1.sync.aligned;")
#define TCG_DEALLOC(tmem, ncols) \
    asm volatile("tcgen05.dealloc.cta_group::1.sync.aligned.b32 %0, %1;" :: "r"(tmem), "r"(ncols))
#define TCG_COMMIT(mbar) \
    asm volatile("tcgen05.commit.cta_group::1.mbarrier::arrive::one.shared::cluster.b64 [%0];" \
                 :: "r"(mbar) : "memory")
#define TCG_FENCE_BEFORE() asm volatile("tcgen05.fence::before_thread_sync;" ::: "memory")
#define TCG_FENCE_AFTER()  asm volatile("tcgen05.fence::after_thread_sync;" ::: "memory")
#define TCG_WAIT_LD()      asm volatile("tcgen05.wait::ld.sync.aligned;" ::: "memory")
#define TCG_WAIT_ST()      asm volatile("tcgen05.wait::st.sync.aligned;" ::: "memory")

#define TCG_LD_X32(r, tmem_addr)                                              \
    asm volatile("tcgen05.ld.sync.aligned.32x32b.x32.b32 "                    \
        "{%0, %1, %2, %3, %4, %5, %6, %7, "                                   \
        " %8, %9, %10, %11, %12, %13, %14, %15, "                             \
        " %16, %17, %18, %19, %20, %21, %22, %23, "                           \
        " %24, %25, %26, %27, %28, %29, %30, %31}, [%32];"                    \
        : "=r"((r)[0]),  "=r"((r)[1]),  "=r"((r)[2]),  "=r"((r)[3]),          \
          "=r"((r)[4]),  "=r"((r)[5]),  "=r"((r)[6]),  "=r"((r)[7]),          \
          "=r"((r)[8]),  "=r"((r)[9]),  "=r"((r)[10]), "=r"((r)[11]),         \
          "=r"((r)[12]), "=r"((r)[13]), "=r"((r)[14]), "=r"((r)[15]),         \
          "=r"((r)[16]), "=r"((r)[17]), "=r"((r)[18]), "=r"((r)[19]),         \
          "=r"((r)[20]), "=r"((r)[21]), "=r"((r)[22]), "=r"((r)[23]),         \
          "=r"((r)[24]), "=r"((r)[25]), "=r"((r)[26]), "=r"((r)[27]),         \
          "=r"((r)[28]), "=r"((r)[29]), "=r"((r)[30]), "=r"((r)[31])          \
        : "r"(tmem_addr))

#define TCG_ST_X32(tmem_addr, r)                                              \
    asm volatile("tcgen05.st.sync.aligned.32x32b.x32.b32 [%0], "              \
        "{%1, %2, %3, %4, %5, %6, %7, %8, "                                   \
        " %9, %10, %11, %12, %13, %14, %15, %16, "                            \
        " %17, %18, %19, %20, %21, %22, %23, %24, "                           \
        " %25, %26, %27, %28, %29, %30, %31, %32};"                           \
        :: "r"(tmem_addr),                                                    \
           "r"((r)[0]),  "r"((r)[1]),  "r"((r)[2]),  "r"((r)[3]),             \
           "r"((r)[4]),  "r"((r)[5]),  "r"((r)[6]),  "r"((r)[7]),             \
           "r"((r)[8]),  "r"((r)[9]),  "r"((r)[10]), "r"((r)[11]),            \
           "r"((r)[12]), "r"((r)[13]), "r"((r)[14]), "r"((r)[15]),            \
           "r"((r)[16]), "r"((r)[17]), "r"((r)[18]), "r"((r)[19]),            \
           "r"((r)[20]), "r"((r)[21]), "r"((r)[22]), "r"((r)[23]),            \
           "r"((r)[24]), "r"((r)[25]), "r"((r)[26]), "r"((r)[27]),            \
           "r"((r)[28]), "r"((r)[29]), "r"((r)[30]), "r"((r)[31])             \
        : "memory")

// TS-mode tf32 MMA: A in TMEM, B in SMEM
__device__ __forceinline__ void mma_tf32_ts(uint32_t d_tmem, uint32_t a_tmem,
                                            uint64_t b_desc, uint32_t idesc,
                                            uint32_t enable_d) {
    asm volatile(
        "{\n\t"
        ".reg .pred p;\n\t"
        "setp.ne.u32 p, %5, 0;\n\t"
        "tcgen05.mma.cta_group::1.kind::tf32 [%0], [%1], %2, %3, {%4, %4, %4, %4}, p;\n\t"
        "}"
        :: "r"(d_tmem), "r"(a_tmem), "l"(b_desc), "r"(idesc), "r"(0u), "r"(enable_d)
        : "memory");
}

// K-major SW128 descriptor (version=1, SBO=64, LBO=1)
__device__ __forceinline__ uint64_t make_desc(uint32_t addr) {
    const uint64_t BASE = (2ull << 61) | (1ull << 46) | (64ull << 32) | (1ull << 16);
    return BASE | ((uint64_t)(addr >> 4) & 0x3FFFull);
}

// blocked-atom SW128 layout for a 128-row x 512-byte tile:
// atom = 8 rows x 128 bytes, 16 atom-rows x 4 atom-cols, atom_off = arow + acol*16
__device__ __forceinline__ uint32_t swz_off(uint32_t row, uint32_t cbyte) {
    uint32_t off = ((row >> 3) + (cbyte >> 7) * 16u) * 1024u
                 + (row & 7u) * 128u + (cbyte & 127u);
    return off ^ ((off >> 3) & 0x70u);
}
#endif  // !RWF_NO_TCGEN05

// ---------------------------------------------------------------------------
// Kernel
// ---------------------------------------------------------------------------
__global__ void __launch_bounds__(NTHREADS, 1)
rwf_tf32_kernel(const float* __restrict__ x, const float* __restrict__ s,
                const float* __restrict__ V, const float* __restrict__ bias,
                float* __restrict__ out, int n_tiles)
{
    extern __shared__ char smem_raw[];

#ifdef RWF_NO_TCGEN05
    // =======================================================================
    // Portable fallback (compute_103 PTX stage): smem-tiled FFMA GEMM.
    // =======================================================================
    float* ws     = (float*)smem_raw;          // [128][129] W' = exp(s)*V
    float* xs     = ws + 128 * 129;            // [128][129] x tile
    float* bias_s = xs + 128 * 129;
    float* sexp_s = bias_s + 128;

    const int tid = threadIdx.x;
    if (tid < 128) {
        sexp_s[tid] = expf(s[tid]);
        bias_s[tid] = bias[tid];
    }
    __syncthreads();
    for (int idx = tid; idx < 128 * 128; idx += NTHREADS) {
        int k = idx >> 7, n = idx & 127;
        ws[k * 129 + n] = sexp_s[k] * V[idx];
    }
    __syncthreads();

    for (int tile = blockIdx.x; tile < n_tiles; tile += gridDim.x) {
        const float* src = x + (size_t)tile * 16384;
        for (int idx = tid; idx < 16384; idx += NTHREADS) {
            int r = idx >> 7, k = idx & 127;
            xs[r * 129 + k] = src[idx];
        }
        __syncthreads();
        if (tid < 256) {
            const int row = tid & 127;
            const int n0  = (tid >> 7) * 64;
            float acc[64];
#pragma unroll
            for (int n = 0; n < 64; n++) acc[n] = bias_s[n0 + n];
            for (int k = 0; k < 128; k++) {
                float xv = xs[row * 129 + k];
#pragma unroll
                for (int n = 0; n < 64; n++)
                    acc[n] = fmaf(xv, ws[k * 129 + n0 + n], acc[n]);
            }
            float* dst = out + ((size_t)tile * 128 + row) * 128 + n0;
#pragma unroll
            for (int n = 0; n < 64; n++) dst[n] = tanh_fast(acc[n]);
        }
        __syncthreads();
    }
#else
    // =======================================================================
    // sm_103a path: TS-mode tcgen05 TF32, 3-deep x ring, 3 D buffers.
    // =======================================================================
    const uint32_t smem0 = smem_u32(smem_raw);
    const uint32_t base  = (smem0 + 1023u) & ~1023u;
    char* gen = smem_raw + (base - smem0);

    float* bias_s = (float*)(gen + OFF_BIAS);
    float* sexp_s = (float*)(gen + OFF_SEXP);

    const int tid = threadIdx.x;
    const int wid = tid >> 5;
    const int lid = tid & 31;

    // ---- prologue -------------------------------------------------------
    if (wid == 8) TCG_ALLOC(base + MB_TMEM, 512);
    if (tid == 0) {
        MBAR_INIT(base + MB_AF + 0, 128);
        MBAR_INIT(base + MB_AF + 8, 128);
        MBAR_INIT(base + MB_AF + 16, 128);
        MBAR_INIT(base + MB_DF + 0, 1);
        MBAR_INIT(base + MB_DF + 8, 1);
        MBAR_INIT(base + MB_DF + 16, 1);
        MBAR_INIT(base + MB_DE + 0, 8);
        MBAR_INIT(base + MB_DE + 8, 8);
        MBAR_INIT(base + MB_DE + 16, 8);
    }
    if (tid < 128) {
        sexp_s[tid] = expf(s[tid]) * W_BIAS_COMP;
        bias_s[tid] = bias[tid];
    }
    __syncthreads();

    uint32_t tmem_base;
    asm volatile("ld.shared.b32 %0, [%1];" : "=r"(tmem_base) : "r"(base + MB_TMEM));

    // W' = exp(s)*V*(1+2^-11) -> TMEM cols 384-511: lane = n, cols = K.
    if (tid < 128) {
        const uint32_t woff = ((uint32_t)tid >> 5) << 21;  // subpartition field
#pragma unroll
        for (int c = 0; c < 4; c++) {
            uint32_t wr[32];
#pragma unroll
            for (int kk = 0; kk < 32; kk++) {
                const int k = c * 32 + kk;
                float w = sexp_s[k] * V[(size_t)k * 128 + tid];
                asm("cvt.rna.tf32.f32 %0, %1;" : "=r"(wr[kk]) : "f"(w));
            }
            TCG_ST_X32(tmem_base + TM_W + c * 32 + woff, wr);
        }
        TCG_WAIT_ST();
    }
    TCG_FENCE_BEFORE();
    __syncthreads();

    const int grid = gridDim.x;
    const int bid  = blockIdx.x;

    if (wid >= 8) {
        // -------- producers (warps 8-11), software-pipelined fills --------
        const int ptid = tid - 256;                 // 0..127
        const float4* __restrict__ x4 = (const float4*)x;
        const uint32_t cb = ((uint32_t)ptid & 31u) * 16u;
        int t = 0, r3 = 0, q3ph = 0;                // t%3, (t/3)&1
        int pr3 = 0, pq3ph = 0;                     // (t-1)%3, ((t-1)/3)&1
        for (int tile = bid; tile < n_tiles; tile += grid, ++t) {
            if (t >= 3) {
                // slot r3 free once MMA(t-3) committed: same slot idx, prev phase
                MBAR_WAIT(base + MB_DF + 8 * r3, q3ph ^ 1);
            }
            const uint32_t abase = base + OFF_A0 + (uint32_t)r3 * A_STRIDE;
            const float4* src = x4 + (size_t)tile * 4096;
#pragma unroll
            for (int i = 0; i < 32; i++) {
                const int f = i * 128 + ptid;
                const uint32_t addr = abase + swz_off((uint32_t)f >> 5, cb);
                CP_ASYNC16(addr, src + f);
            }
            CP_COMMIT();
            if (t > 0) {
                CP_WAIT1();                         // fill(t-1) complete
                FENCE_ASYNC_SHARED();
                MBAR_ARRIVE(base + MB_AF + 8 * pr3);
                if (wid == 8) {
                    const int u = t - 1;            // u%3 == pr3
                    MBAR_WAIT(base + MB_AF + 8 * pr3, pq3ph);       // B ready
                    if (u >= 3)                                     // D drained
                        MBAR_WAIT(base + MB_DE + 8 * pr3, pq3ph ^ 1);
                    TCG_FENCE_AFTER();
                    if (elect_one()) {
                        const uint32_t d = tmem_base + 128u * (uint32_t)pr3;
                        const uint64_t bd = make_desc(base + OFF_A0 + (uint32_t)pr3 * A_STRIDE);
#pragma unroll
                        for (int k = 0; k < 16; k++) {
                            const uint64_t koff = (uint64_t)((k >> 2) * 1024 + (k & 3) * 2);
                            mma_tf32_ts(d, tmem_base + TM_W + k * 8, bd + koff,
                                        IDESC_TF32, (k > 0) ? 1u : 0u);
                        }
                        TCG_COMMIT(base + MB_DF + 8 * pr3);
                    }
                }
            }
            pr3 = r3; pq3ph = q3ph;
            if (++r3 == 3) { r3 = 0; q3ph ^= 1; }
        }
        // tail: finish last fill + last MMA
        if (t > 0) {
            const int u = t - 1;
            CP_WAIT0();
            FENCE_ASYNC_SHARED();
            MBAR_ARRIVE(base + MB_AF + 8 * pr3);
            if (wid == 8) {
                MBAR_WAIT(base + MB_AF + 8 * pr3, pq3ph);
                if (u >= 3)
                    MBAR_WAIT(base + MB_DE + 8 * pr3, pq3ph ^ 1);
                TCG_FENCE_AFTER();
                if (elect_one()) {
                    const uint32_t d = tmem_base + 128u * (uint32_t)pr3;
                    const uint64_t bd = make_desc(base + OFF_A0 + (uint32_t)pr3 * A_STRIDE);
#pragma unroll
                    for (int k = 0; k < 16; k++) {
                        const uint64_t koff = (uint64_t)((k >> 2) * 1024 + (k & 3) * 2);
                        mma_tf32_ts(d, tmem_base + TM_W + k * 8, bd + koff,
                                    IDESC_TF32, (k > 0) ? 1u : 0u);
                    }
                    TCG_COMMIT(base + MB_DF + 8 * pr3);
                }
            }
        }
    } else {
        // -------- epilogue (warps 0-7, 256 threads), direct stores --------
        // D transposed: lane = n (contiguous in out), TMEM col = m.
        const int sp   = wid & 3;        // TMEM subpartition (n block)
        const int half = wid >> 2;       // m half (0: rows 0-63, 1: 64-127)
        const int n    = sp * 32 + lid;  // this thread's output column
        const int mbase = half * 64;
        const float bn = bias_s[n];
        int t = 0, r3 = 0, q3ph = 0;
        for (int tile = bid; tile < n_tiles; tile += grid, ++t) {
            MBAR_WAIT(base + MB_DF + 8 * r3, q3ph);
            TCG_FENCE_AFTER();
            const uint32_t dt = tmem_base + 128u * (uint32_t)r3 + mbase;
            uint32_t ra[32], rb[32];
            TCG_LD_X32(ra, dt);
            TCG_LD_X32(rb, dt + 32);
            TCG_WAIT_LD();
            TCG_FENCE_BEFORE();
            // D buffer drained into registers -> release it immediately
            if (elect_one()) MBAR_ARRIVE(base + MB_DE + 8 * r3);
            // fully-coalesced streaming stores: 32 lanes x 4B contiguous
            float* dst = out + ((size_t)tile * 128 + (size_t)mbase) * 128 + n;
#pragma unroll
            for (int j = 0; j < 32; j++)
                __stcs(dst + (size_t)j * 128, tanh_fast(__uint_as_float(ra[j]) + bn));
#pragma unroll
            for (int j = 0; j < 32; j++)
                __stcs(dst + (size_t)(32 + j) * 128, tanh_fast(__uint_as_float(rb[j]) + bn));
            if (++r3 == 3) { r3 = 0; q3ph ^= 1; }
        }
    }

    // ---- teardown ---------------------------------------------------------
    __syncthreads();
    if (wid == 8) {
        TCG_RELINQ();
        TCG_DEALLOC(tmem_base, 512);
    }
#endif  // RWF_NO_TCGEN05
}

// ---------------------------------------------------------------------------
// Launch
// ---------------------------------------------------------------------------
extern "C" void kernel_launch(void* const* d_in, const int* in_sizes, int n_in,
                              void* d_out, int out_size)
{
    const float* x    = (const float*)d_in[0];
    const float* s    = (const float*)d_in[1];
    const float* V    = (const float*)d_in[2];
    const float* bias = (const float*)d_in[3];
    float* out = (float*)d_out;

    const long long M = (long long)in_sizes[0] / 128;   // rows of x
    const int n_tiles = (int)(M >> 7);                  // 128-row tiles (8192)

    cudaFuncSetAttribute(rwf_tf32_kernel,
                         cudaFuncAttributeMaxDynamicSharedMemorySize, SMEM_BYTES);

    int sms = 148;
    int dev = 0;
    cudaGetDevice(&dev);
    cudaDeviceGetAttribute(&sms, cudaDevAttrMultiProcessorCount, dev);
    int grid = (sms < n_tiles) ? sms : n_tiles;
    if (grid < 1) grid = 1;

    rwf_tf32_kernel<<<grid, NTHREADS, SMEM_BYTES>>>(x, s, V, bias, out, n_tiles);
}

// round 14
// speedup vs baseline: 1.0036x; 1.0036x over previous
#include <cuda_runtime.h>
#include <cuda.h>
#include <cstdint>

// ============================================================================
// out[m,n] = tanh( sum_k x[m,k] * (exp(s[k]) * V[k,n]) + bias[n] )
// M = 1048576, K = N = 128, fp32 in/out.
//
// sm_103a: persistent warp-specialized tcgen05 TF32 TS-mode GEMM (384 thr):
//   W' = exp(s)*V (tf32, bias-compensated) lives in TMEM (cols 384-511) as
//   the A operand. x tiles stream through a 3-deep smem ring (B operand);
//   ring slots freed by MMA commit (DF). D[n,m] transposed, TRIPLE-buffered
//   in TMEM cols 0-383 -> MMA(u) only needs epi(u-3) drained.
//   Epilogue stores directly: lane = n = contiguous output direction, so
//   STG.32.CS is fully coalesced (no smem bounce); DE signaled right after
//   LDTM drains D into registers.
//   warps 0-7  : epilogue (LDTM x2 + early DE + bias + tanh.approx + STG.CS)
//   warps 8-11 : producers (cp.async.cg, software-pipelined wait_group 1)
//   warp  8    : issues 16x tcgen05.mma.kind::tf32 TS per tile
// compute_103 (portable PTX) stage: smem-tiled FFMA fallback.
// ============================================================================

#if defined(__CUDA_ARCH__) && !defined(__CUDA_ARCH_FEAT_SM103_ALL) && !defined(__CUDA_ARCH_FEAT_SM100_ALL)
#define RWF_NO_TCGEN05 1
#endif

#define NTHREADS 384
#define SMEM_BYTES 199680
#define IDESC_TF32 0x8200910u   // cF32 | aTF32 | bTF32 | N=128 | M=128

// offsets from 1024-aligned smem base (tcgen05 path)
#define OFF_BIAS 128
#define OFF_SEXP 768
#define OFF_A0   2048           // 3 x 64KB x-tile ring
#define A_STRIDE 65536

// mbarrier offsets (from aligned base)
#define MB_AF   0               // 3 x 8B (B tile filled)
#define MB_DF   24              // 3 x 8B (MMA committed; B consumed, D full)
#define MB_DE   48              // 3 x 8B (D drained by epilogue LDTM)
#define MB_TMEM 72

// TMEM column map: D buffers at 128*(u%3), W at 384
#define TM_W  384

// truncation bias compensation: E[trunc rel err] = -2^-11 on B (x, HW-truncated)
#define W_BIAS_COMP 1.00048828125f

// ---------------------------------------------------------------------------
// Generic helpers (portable)
// ---------------------------------------------------------------------------
__device__ __forceinline__ uint32_t smem_u32(const void* p) {
    uint32_t a;
    asm("{ .reg .u64 t; cvta.to.shared.u64 t, %1; cvt.u32.u64 %0, t; }"
        : "=r"(a) : "l"(p));
    return a;
}

__device__ __forceinline__ float tanh_fast(float z) {
    float r;
    asm("tanh.approx.f32 %0, %1;" : "=f"(r) : "f"(z));
    return r;
}

#ifndef RWF_NO_TCGEN05
// ---------------------------------------------------------------------------
// sm_103a-only helpers
// ---------------------------------------------------------------------------
__device__ __forceinline__ uint32_t elect_one() {
    uint32_t r;
    asm volatile("{ .reg .pred p; elect.sync _|p, 0xFFFFFFFF; selp.b32 %0, 1, 0, p; }"
                 : "=r"(r));
    return r;
}

#define MBAR_INIT(addr, cnt) \
    asm volatile("mbarrier.init.shared.b64 [%0], %1;" :: "r"(addr), "r"(cnt) : "memory")

#define MBAR_ARRIVE(addr) \
    asm volatile("mbarrier.arrive.shared.b64 _, [%0];" :: "r"(addr) : "memory")

#define MBAR_WAIT(addr, ph) do {                                              \
    uint32_t _a = (addr), _p = (ph), _d;                                      \
    asm volatile("{\n\t.reg .pred p;\n\t"                                     \
        "mbarrier.try_wait.parity.acquire.cta.shared::cta.b64 p, [%1], %2;\n\t" \
        "selp.b32 %0, 1, 0, p;\n\t}"                                          \
        : "=r"(_d) : "r"(_a), "r"(_p) : "memory");                            \
    while (!_d) {                                                             \
        asm volatile("{\n\t.reg .pred p;\n\t"                                 \
            "mbarrier.try_wait.parity.acquire.cta.shared::cta.b64 p, [%1], %2, 0x989680;\n\t" \
            "selp.b32 %0, 1, 0, p;\n\t}"                                      \
            : "=r"(_d) : "r"(_a), "r"(_p) : "memory");                        \
    }                                                                         \
} while (0)

#define FENCE_ASYNC_SHARED() \
    asm volatile("fence.proxy.async.shared::cta;" ::: "memory")

#define CP_ASYNC16(saddr, gptr) \
    asm volatile("cp.async.cg.shared.global [%0], [%1], 16;" \
                 :: "r"(saddr), "l"(gptr) : "memory")
#define CP_COMMIT() asm volatile("cp.async.commit_group;" ::: "memory")
#define CP_WAIT1()  asm volatile("cp.async.wait_group 1;" ::: "memory")
#define CP_WAIT0()  asm volatile("cp.async.wait_group 0;" ::: "memory")

#define TCG_ALLOC(smem_addr, ncols) \
    asm volatile("tcgen05.alloc.cta_group::1.sync.aligned.shared::cta.b32 [%0], %1;" \
                 :: "r"(smem_addr), "r"(ncols) : "memory")
#define TCG_RELINQ() \
    asm volatile("tcgen05.relinquish_alloc_permit.cta_group::1.sync.aligned;")
#define TCG_DEALLOC(tmem, ncols) \
    asm volatile("tcgen05.dealloc.cta_group::1.sync.aligned.b32 %0, %1;" :: "r"(tmem), "r"(ncols))
#define TCG_COMMIT(mbar) \
    asm volatile("tcgen05.commit.cta_group::1.mbarrier::arrive::one.shared::cluster.b64 [%0];" \
                 :: "r"(mbar) : "memory")
#define TCG_FENCE_BEFORE() asm volatile("tcgen05.fence::before_thread_sync;" ::: "memory")
#define TCG_FENCE_AFTER()  asm volatile("tcgen05.fence::after_thread_sync;" ::: "memory")
#define TCG_WAIT_LD()      asm volatile("tcgen05.wait::ld.sync.aligned;" ::: "memory")
#define TCG_WAIT_ST()      asm volatile("tcgen05.wait::st.sync.aligned;" ::: "memory")

#define TCG_LD_X32(r, tmem_addr)                                              \
    asm volatile("tcgen05.ld.sync.aligned.32x32b.x32.b32 "                    \
        "{%0, %1, %2, %3, %4, %5, %6, %7, "                                   \
        " %8, %9, %10, %11, %12, %13, %14, %15, "                             \
        " %16, %17, %18, %19, %20, %21, %22, %23, "                           \
        " %24, %25, %26, %27, %28, %29, %30, %31}, [%32];"                    \
        : "=r"((r)[0]),  "=r"((r)[1]),  "=r"((r)[2]),  "=r"((r)[3]),          \
          "=r"((r)[4]),  "=r"((r)[5]),  "=r"((r)[6]),  "=r"((r)[7]),          \
          "=r"((r)[8]),  "=r"((r)[9]),  "=r"((r)[10]), "=r"((r)[11]),         \
          "=r"((r)[12]), "=r"((r)[13]), "=r"((r)[14]), "=r"((r)[15]),         \
          "=r"((r)[16]), "=r"((r)[17]), "=r"((r)[18]), "=r"((r)[19]),         \
          "=r"((r)[20]), "=r"((r)[21]), "=r"((r)[22]), "=r"((r)[23]),         \
          "=r"((r)[24]), "=r"((r)[25]), "=r"((r)[26]), "=r"((r)[27]),         \
          "=r"((r)[28]), "=r"((r)[29]), "=r"((r)[30]), "=r"((r)[31])          \
        : "r"(tmem_addr))

#define TCG_ST_X32(tmem_addr, r)                                              \
    asm volatile("tcgen05.st.sync.aligned.32x32b.x32.b32 [%0], "              \
        "{%1, %2, %3, %4, %5, %6, %7, %8, "                                   \
        " %9, %10, %11, %12, %13, %14, %15, %16, "                            \
        " %17, %18, %19, %20, %21, %22, %23, %24, "                           \
        " %25, %26, %27, %28, %29, %30, %31, %32};"                           \
        :: "r"(tmem_addr),                                                    \
           "r"((r)[0]),  "r"((r)[1]),  "r"((r)[2]),  "r"((r)[3]),             \
           "r"((r)[4]),  "r"((r)[5]),  "r"((r)[6]),  "r"((r)[7]),             \
           "r"((r)[8]),  "r"((r)[9]),  "r"((r)[10]), "r"((r)[11]),            \
           "r"((r)[12]), "r"((r)[13]), "r"((r)[14]), "r"((r)[15]),            \
           "r"((r)[16]), "r"((r)[17]), "r"((r)[18]), "r"((r)[19]),            \
           "r"((r)[20]), "r"((r)[21]), "r"((r)[22]), "r"((r)[23]),            \
           "r"((r)[24]), "r"((r)[25]), "r"((r)[26]), "r"((r)[27]),            \
           "r"((r)[28]), "r"((r)[29]), "r"((r)[30]), "r"((r)[31])             \
        : "memory")

// TS-mode tf32 MMA: A in TMEM, B in SMEM
__device__ __forceinline__ void mma_tf32_ts(uint32_t d_tmem, uint32_t a_tmem,
                                            uint64_t b_desc, uint32_t idesc,
                                            uint32_t enable_d) {
    asm volatile(
        "{\n\t"
        ".reg .pred p;\n\t"
        "setp.ne.u32 p, %5, 0;\n\t"
        "tcgen05.mma.cta_group::1.kind::tf32 [%0], [%1], %2, %3, {%4, %4, %4, %4}, p;\n\t"
        "}"
        :: "r"(d_tmem), "r"(a_tmem), "l"(b_desc), "r"(idesc), "r"(0u), "r"(enable_d)
        : "memory");
}

// K-major SW128 descriptor (version=1, SBO=64, LBO=1)
__device__ __forceinline__ uint64_t make_desc(uint32_t addr) {
    const uint64_t BASE = (2ull << 61) | (1ull << 46) | (64ull << 32) | (1ull << 16);
    return BASE | ((uint64_t)(addr >> 4) & 0x3FFFull);
}

// blocked-atom SW128 layout for a 128-row x 512-byte tile:
// atom = 8 rows x 128 bytes, 16 atom-rows x 4 atom-cols, atom_off = arow + acol*16
__device__ __forceinline__ uint32_t swz_off(uint32_t row, uint32_t cbyte) {
    uint32_t off = ((row >> 3) + (cbyte >> 7) * 16u) * 1024u
                 + (row & 7u) * 128u + (cbyte & 127u);
    return off ^ ((off >> 3) & 0x70u);
}
#endif  // !RWF_NO_TCGEN05

// ---------------------------------------------------------------------------
// Kernel
// ---------------------------------------------------------------------------
__global__ void __launch_bounds__(NTHREADS, 1)
rwf_tf32_kernel(const float* __restrict__ x, const float* __restrict__ s,
                const float* __restrict__ V, const float* __restrict__ bias,
                float* __restrict__ out, int n_tiles)
{
    extern __shared__ char smem_raw[];

#ifdef RWF_NO_TCGEN05
    // =======================================================================
    // Portable fallback (compute_103 PTX stage): smem-tiled FFMA GEMM.
    // =======================================================================
    float* ws     = (float*)smem_raw;          // [128][129] W' = exp(s)*V
    float* xs     = ws + 128 * 129;            // [128][129] x tile
    float* bias_s = xs + 128 * 129;
    float* sexp_s = bias_s + 128;

    const int tid = threadIdx.x;
    if (tid < 128) {
        sexp_s[tid] = expf(s[tid]);
        bias_s[tid] = bias[tid];
    }
    __syncthreads();
    for (int idx = tid; idx < 128 * 128; idx += NTHREADS) {
        int k = idx >> 7, n = idx & 127;
        ws[k * 129 + n] = sexp_s[k] * V[idx];
    }
    __syncthreads();

    for (int tile = blockIdx.x; tile < n_tiles; tile += gridDim.x) {
        const float* src = x + (size_t)tile * 16384;
        for (int idx = tid; idx < 16384; idx += NTHREADS) {
            int r = idx >> 7, k = idx & 127;
            xs[r * 129 + k] = src[idx];
        }
        __syncthreads();
        if (tid < 256) {
            const int row = tid & 127;
            const int n0  = (tid >> 7) * 64;
            float acc[64];
#pragma unroll
            for (int n = 0; n < 64; n++) acc[n] = bias_s[n0 + n];
            for (int k = 0; k < 128; k++) {
                float xv = xs[row * 129 + k];
#pragma unroll
                for (int n = 0; n < 64; n++)
                    acc[n] = fmaf(xv, ws[k * 129 + n0 + n], acc[n]);
            }
            float* dst = out + ((size_t)tile * 128 + row) * 128 + n0;
#pragma unroll
            for (int n = 0; n < 64; n++) dst[n] = tanh_fast(acc[n]);
        }
        __syncthreads();
    }
#else
    // =======================================================================
    // sm_103a path: TS-mode tcgen05 TF32, 3-deep x ring, 3 D buffers.
    // =======================================================================
    const uint32_t smem0 = smem_u32(smem_raw);
    const uint32_t base  = (smem0 + 1023u) & ~1023u;
    char* gen = smem_raw + (base - smem0);

    float* bias_s = (float*)(gen + OFF_BIAS);
    float* sexp_s = (float*)(gen + OFF_SEXP);

    const int tid = threadIdx.x;
    const int wid = tid >> 5;
    const int lid = tid & 31;

    // ---- prologue -------------------------------------------------------
    if (wid == 8) TCG_ALLOC(base + MB_TMEM, 512);
    if (tid == 0) {
        MBAR_INIT(base + MB_AF + 0, 128);
        MBAR_INIT(base + MB_AF + 8, 128);
        MBAR_INIT(base + MB_AF + 16, 128);
        MBAR_INIT(base + MB_DF + 0, 1);
        MBAR_INIT(base + MB_DF + 8, 1);
        MBAR_INIT(base + MB_DF + 16, 1);
        MBAR_INIT(base + MB_DE + 0, 8);
        MBAR_INIT(base + MB_DE + 8, 8);
        MBAR_INIT(base + MB_DE + 16, 8);
    }
    if (tid < 128) {
        sexp_s[tid] = expf(s[tid]) * W_BIAS_COMP;
        bias_s[tid] = bias[tid];
    }
    __syncthreads();

    uint32_t tmem_base;
    asm volatile("ld.shared.b32 %0, [%1];" : "=r"(tmem_base) : "r"(base + MB_TMEM));

    // W' = exp(s)*V*(1+2^-11) -> TMEM cols 384-511: lane = n, cols = K.
    if (tid < 128) {
        const uint32_t woff = ((uint32_t)tid >> 5) << 21;  // subpartition field
#pragma unroll
        for (int c = 0; c < 4; c++) {
            uint32_t wr[32];
#pragma unroll
            for (int kk = 0; kk < 32; kk++) {
                const int k = c * 32 + kk;
                float w = sexp_s[k] * V[(size_t)k * 128 + tid];
                asm("cvt.rna.tf32.f32 %0, %1;" : "=r"(wr[kk]) : "f"(w));
            }
            TCG_ST_X32(tmem_base + TM_W + c * 32 + woff, wr);
        }
        TCG_WAIT_ST();
    }
    TCG_FENCE_BEFORE();
    __syncthreads();

    const int grid = gridDim.x;
    const int bid  = blockIdx.x;

    if (wid >= 8) {
        // -------- producers (warps 8-11), software-pipelined fills --------
        const int ptid = tid - 256;                 // 0..127
        const float4* __restrict__ x4 = (const float4*)x;
        const uint32_t cb = ((uint32_t)ptid & 31u) * 16u;
        int t = 0, r3 = 0, q3ph = 0;                // t%3, (t/3)&1
        int pr3 = 0, pq3ph = 0;                     // (t-1)%3, ((t-1)/3)&1
        for (int tile = bid; tile < n_tiles; tile += grid, ++t) {
            if (t >= 3) {
                // slot r3 free once MMA(t-3) committed: same slot idx, prev phase
                MBAR_WAIT(base + MB_DF + 8 * r3, q3ph ^ 1);
            }
            const uint32_t abase = base + OFF_A0 + (uint32_t)r3 * A_STRIDE;
            const float4* src = x4 + (size_t)tile * 4096;
#pragma unroll
            for (int i = 0; i < 32; i++) {
                const int f = i * 128 + ptid;
                const uint32_t addr = abase + swz_off((uint32_t)f >> 5, cb);
                CP_ASYNC16(addr, src + f);
            }
            CP_COMMIT();
            if (t > 0) {
                CP_WAIT1();                         // fill(t-1) complete
                FENCE_ASYNC_SHARED();
                MBAR_ARRIVE(base + MB_AF + 8 * pr3);
                if (wid == 8) {
                    const int u = t - 1;            // u%3 == pr3
                    MBAR_WAIT(base + MB_AF + 8 * pr3, pq3ph);       // B ready
                    if (u >= 3)                                     // D drained
                        MBAR_WAIT(base + MB_DE + 8 * pr3, pq3ph ^ 1);
                    TCG_FENCE_AFTER();
                    if (elect_one()) {
                        const uint32_t d = tmem_base + 128u * (uint32_t)pr3;
                        const uint64_t bd = make_desc(base + OFF_A0 + (uint32_t)pr3 * A_STRIDE);
#pragma unroll
                        for (int k = 0; k < 16; k++) {
                            const uint64_t koff = (uint64_t)((k >> 2) * 1024 + (k & 3) * 2);
                            mma_tf32_ts(d, tmem_base + TM_W + k * 8, bd + koff,
                                        IDESC_TF32, (k > 0) ? 1u : 0u);
                        }
                        TCG_COMMIT(base + MB_DF + 8 * pr3);
                    }
                }
            }
            pr3 = r3; pq3ph = q3ph;
            if (++r3 == 3) { r3 = 0; q3ph ^= 1; }
        }
        // tail: finish last fill + last MMA
        if (t > 0) {
            const int u = t - 1;
            CP_WAIT0();
            FENCE_ASYNC_SHARED();
            MBAR_ARRIVE(base + MB_AF + 8 * pr3);
            if (wid == 8) {
                MBAR_WAIT(base + MB_AF + 8 * pr3, pq3ph);
                if (u >= 3)
                    MBAR_WAIT(base + MB_DE + 8 * pr3, pq3ph ^ 1);
                TCG_FENCE_AFTER();
                if (elect_one()) {
                    const uint32_t d = tmem_base + 128u * (uint32_t)pr3;
                    const uint64_t bd = make_desc(base + OFF_A0 + (uint32_t)pr3 * A_STRIDE);
#pragma unroll
                    for (int k = 0; k < 16; k++) {
                        const uint64_t koff = (uint64_t)((k >> 2) * 1024 + (k & 3) * 2);
                        mma_tf32_ts(d, tmem_base + TM_W + k * 8, bd + koff,
                                    IDESC_TF32, (k > 0) ? 1u : 0u);
                    }
                    TCG_COMMIT(base + MB_DF + 8 * pr3);
                }
            }
        }
    } else {
        // -------- epilogue (warps 0-7, 256 threads), direct stores --------
        // D transposed: lane = n (contiguous in out), TMEM col = m.
        const int sp   = wid & 3;        // TMEM subpartition (n block)
        const int half = wid >> 2;       // m half (0: rows 0-63, 1: 64-127)
        const int n    = sp * 32 + lid;  // this thread's output column
        const int mbase = half * 64;
        const float bn = bias_s[n];
        int t = 0, r3 = 0, q3ph = 0;
        for (int tile = bid; tile < n_tiles; tile += grid, ++t) {
            MBAR_WAIT(base + MB_DF + 8 * r3, q3ph);
            TCG_FENCE_AFTER();
            const uint32_t dt = tmem_base + 128u * (uint32_t)r3 + mbase;
            uint32_t ra[32], rb[32];
            TCG_LD_X32(ra, dt);
            TCG_LD_X32(rb, dt + 32);
            TCG_WAIT_LD();
            TCG_FENCE_BEFORE();
            // D buffer drained into registers -> release it immediately
            if (elect_one()) MBAR_ARRIVE(base + MB_DE + 8 * r3);
            // fully-coalesced streaming stores: 32 lanes x 4B contiguous
            float* dst = out + ((size_t)tile * 128 + (size_t)mbase) * 128 + n;
#pragma unroll
            for (int j = 0; j < 32; j++)
                __stcs(dst + (size_t)j * 128, tanh_fast(__uint_as_float(ra[j]) + bn));
#pragma unroll
            for (int j = 0; j < 32; j++)
                __stcs(dst + (size_t)(32 + j) * 128, tanh_fast(__uint_as_float(rb[j]) + bn));
            if (++r3 == 3) { r3 = 0; q3ph ^= 1; }
        }
    }

    // ---- teardown ---------------------------------------------------------
    __syncthreads();
    if (wid == 8) {
        TCG_RELINQ();
        TCG_DEALLOC(tmem_base, 512);
    }
#endif  // RWF_NO_TCGEN05
}

// ---------------------------------------------------------------------------
// Launch
// ---------------------------------------------------------------------------
extern "C" void kernel_launch(void* const* d_in, const int* in_sizes, int n_in,
                              void* d_out, int out_size)
{
    const float* x    = (const float*)d_in[0];
    const float* s    = (const float*)d_in[1];
    const float* V    = (const float*)d_in[2];
    const float* bias = (const float*)d_in[3];
    float* out = (float*)d_out;

    const long long M = (long long)in_sizes[0] / 128;   // rows of x
    const int n_tiles = (int)(M >> 7);                  // 128-row tiles (8192)

    cudaFuncSetAttribute(rwf_tf32_kernel,
                         cudaFuncAttributeMaxDynamicSharedMemorySize, SMEM_BYTES);

    int sms = 148;
    int dev = 0;
    cudaGetDevice(&dev);
    cudaDeviceGetAttribute(&sms, cudaDevAttrMultiProcessorCount, dev);
    int grid = (sms < n_tiles) ? sms : n_tiles;
    if (grid < 1) grid = 1;

    rwf_tf32_kernel<<<grid, NTHREADS, SMEM_BYTES>>>(x, s, V, bias, out, n_tiles);
}

// round 16
// speedup vs baseline: 1.0117x; 1.0081x over previous
#include <cuda_runtime.h>
#include <cuda.h>
#include <cstdint>

// ============================================================================
// out[m,n] = tanh( sum_k x[m,k] * (exp(s[k]) * V[k,n]) + bias[n] )
// M = 1048576, K = N = 128, fp32 in/out.
//
// sm_103a: persistent warp-specialized tcgen05 TF32 TS-mode GEMM (416 thr):
//   W' = exp(s)*V (tf32, bias-compensated) in TMEM cols 384-511 (A operand),
//   built by epilogue warps 0-3 OVERLAPPED with the first fills (WF gate).
//   x tiles stream through a 3-deep smem ring (B operand); slots freed by
//   MMA commit (DF). D[n,m] triple-buffered (cols 0-383).
//   warps 0-7  : epilogue (LDTM x2 + early DE + bias + tanh.approx + STG.CS,
//                fully coalesced: lane = n = contiguous output direction)
//   warps 8-11 : pure producers (plain cp.async.cg, software-pipelined)
//   warp  12   : dedicated MMA issuer (wait WF/AF/DE -> 16x tf32 TS -> DF)
// compute_103 (portable PTX) stage: smem-tiled FFMA fallback.
// ============================================================================

#if defined(__CUDA_ARCH__) && !defined(__CUDA_ARCH_FEAT_SM103_ALL) && !defined(__CUDA_ARCH_FEAT_SM100_ALL)
#define RWF_NO_TCGEN05 1
#endif

#define NTHREADS 416
#define SMEM_BYTES 199680
#define IDESC_TF32 0x8200910u   // cF32 | aTF32 | bTF32 | N=128 | M=128

// offsets from 1024-aligned smem base (tcgen05 path)
#define OFF_BIAS 128
#define OFF_SEXP 768
#define OFF_A0   2048           // 3 x 64KB x-tile ring
#define A_STRIDE 65536

// mbarrier offsets (from aligned base)
#define MB_AF   0               // 3 x 8B (B tile filled)
#define MB_DF   24              // 3 x 8B (MMA committed; B consumed, D full)
#define MB_DE   48              // 3 x 8B (D drained by epilogue LDTM)
#define MB_WF   72              // W resident in TMEM (gates first MMA)
#define MB_TMEM 80

// TMEM column map: D buffers at 128*(u%3), W at 384
#define TM_W  384

// truncation bias compensation: E[trunc rel err] = -2^-11 on B (x, HW-truncated)
#define W_BIAS_COMP 1.00048828125f

// ---------------------------------------------------------------------------
// Generic helpers (portable)
// ---------------------------------------------------------------------------
__device__ __forceinline__ uint32_t smem_u32(const void* p) {
    uint32_t a;
    asm("{ .reg .u64 t; cvta.to.shared.u64 t, %1; cvt.u32.u64 %0, t; }"
        : "=r"(a) : "l"(p));
    return a;
}

__device__ __forceinline__ float tanh_fast(float z) {
    float r;
    asm("tanh.approx.f32 %0, %1;" : "=f"(r) : "f"(z));
    return r;
}

#ifndef RWF_NO_TCGEN05
// ---------------------------------------------------------------------------
// sm_103a-only helpers
// ---------------------------------------------------------------------------
__device__ __forceinline__ uint32_t elect_one() {
    uint32_t r;
    asm volatile("{ .reg .pred p; elect.sync _|p, 0xFFFFFFFF; selp.b32 %0, 1, 0, p; }"
                 : "=r"(r));
    return r;
}

#define MBAR_INIT(addr, cnt) \
    asm volatile("mbarrier.init.shared.b64 [%0], %1;" :: "r"(addr), "r"(cnt) : "memory")

#define MBAR_ARRIVE(addr) \
    asm volatile("mbarrier.arrive.shared.b64 _, [%0];" :: "r"(addr) : "memory")

#define MBAR_WAIT(addr, ph) do {                                              \
    uint32_t _a = (addr), _p = (ph), _d;                                      \
    asm volatile("{\n\t.reg .pred p;\n\t"                                     \
        "mbarrier.try_wait.parity.acquire.cta.shared::cta.b64 p, [%1], %2;\n\t" \
        "selp.b32 %0, 1, 0, p;\n\t}"                                          \
        : "=r"(_d) : "r"(_a), "r"(_p) : "memory");                            \
    while (!_d) {                                                             \
        asm volatile("{\n\t.reg .pred p;\n\t"                                 \
            "mbarrier.try_wait.parity.acquire.cta.shared::cta.b64 p, [%1], %2, 0x989680;\n\t" \
            "selp.b32 %0, 1, 0, p;\n\t}"                                      \
            : "=r"(_d) : "r"(_a), "r"(_p) : "memory");                        \
    }                                                                         \
} while (0)

#define FENCE_ASYNC_SHARED() \
    asm volatile("fence.proxy.async.shared::cta;" ::: "memory")

#define CP_ASYNC16(saddr, gptr) \
    asm volatile("cp.async.cg.shared.global [%0], [%1], 16;" \
                 :: "r"(saddr), "l"(gptr) : "memory")
#define CP_COMMIT() asm volatile("cp.async.commit_group;" ::: "memory")
#define CP_WAIT1()  asm volatile("cp.async.wait_group 1;" ::: "memory")
#define CP_WAIT0()  asm volatile("cp.async.wait_group 0;" ::: "memory")

#define TCG_ALLOC(smem_addr, ncols) \
    asm volatile("tcgen05.alloc.cta_group::1.sync.aligned.shared::cta.b32 [%0], %1;" \
                 :: "r"(smem_addr), "r"(ncols) : "memory")
#define TCG_RELINQ() \
    asm volatile("tcgen05.relinquish_alloc_permit.cta_group::1.sync.aligned;")
#define TCG_DEALLOC(tmem, ncols) \
    asm volatile("tcgen05.dealloc.cta_group::1.sync.aligned.b32 %0, %1;" :: "r"(tmem), "r"(ncols))
#define TCG_COMMIT(mbar) \
    asm volatile("tcgen05.commit.cta_group::1.mbarrier::arrive::one.shared::cluster.b64 [%0];" \
                 :: "r"(mbar) : "memory")
#define TCG_FENCE_BEFORE() asm volatile("tcgen05.fence::before_thread_sync;" ::: "memory")
#define TCG_FENCE_AFTER()  asm volatile("tcgen05.fence::after_thread_sync;" ::: "memory")
#define TCG_WAIT_LD()      asm volatile("tcgen05.wait::ld.sync.aligned;" ::: "memory")
#define TCG_WAIT_ST()      asm volatile("tcgen05.wait::st.sync.aligned;" ::: "memory")

#define TCG_LD_X32(r, tmem_addr)                                              \
    asm volatile("tcgen05.ld.sync.aligned.32x32b.x32.b32 "                    \
        "{%0, %1, %2, %3, %4, %5, %6, %7, "                                   \
        " %8, %9, %10, %11, %12, %13, %14, %15, "                             \
        " %16, %17, %18, %19, %20, %21, %22, %23, "                           \
        " %24, %25, %26, %27, %28, %29, %30, %31}, [%32];"                    \
        : "=r"((r)[0]),  "=r"((r)[1]),  "=r"((r)[2]),  "=r"((r)[3]),          \
          "=r"((r)[4]),  "=r"((r)[5]),  "=r"((r)[6]),  "=r"((r)[7]),          \
          "=r"((r)[8]),  "=r"((r)[9]),  "=r"((r)[10]), "=r"((r)[11]),         \
          "=r"((r)[12]), "=r"((r)[13]), "=r"((r)[14]), "=r"((r)[15]),         \
          "=r"((r)[16]), "=r"((r)[17]), "=r"((r)[18]), "=r"((r)[19]),         \
          "=r"((r)[20]), "=r"((r)[21]), "=r"((r)[22]), "=r"((r)[23]),         \
          "=r"((r)[24]), "=r"((r)[25]), "=r"((r)[26]), "=r"((r)[27]),         \
          "=r"((r)[28]), "=r"((r)[29]), "=r"((r)[30]), "=r"((r)[31])          \
        : "r"(tmem_addr))

#define TCG_ST_X32(tmem_addr, r)                                              \
    asm volatile("tcgen05.st.sync.aligned.32x32b.x32.b32 [%0], "              \
        "{%1, %2, %3, %4, %5, %6, %7, %8, "                                   \
        " %9, %10, %11, %12, %13, %14, %15, %16, "                            \
        " %17, %18, %19, %20, %21, %22, %23, %24, "                           \
        " %25, %26, %27, %28, %29, %30, %31, %32};"                           \
        :: "r"(tmem_addr),                                                    \
           "r"((r)[0]),  "r"((r)[1]),  "r"((r)[2]),  "r"((r)[3]),             \
           "r"((r)[4]),  "r"((r)[5]),  "r"((r)[6]),  "r"((r)[7]),             \
           "r"((r)[8]),  "r"((r)[9]),  "r"((r)[10]), "r"((r)[11]),            \
           "r"((r)[12]), "r"((r)[13]), "r"((r)[14]), "r"((r)[15]),            \
           "r"((r)[16]), "r"((r)[17]), "r"((r)[18]), "r"((r)[19]),            \
           "r"((r)[20]), "r"((r)[21]), "r"((r)[22]), "r"((r)[23]),            \
           "r"((r)[24]), "r"((r)[25]), "r"((r)[26]), "r"((r)[27]),            \
           "r"((r)[28]), "r"((r)[29]), "r"((r)[30]), "r"((r)[31])             \
        : "memory")

// TS-mode tf32 MMA: A in TMEM, B in SMEM
__device__ __forceinline__ void mma_tf32_ts(uint32_t d_tmem, uint32_t a_tmem,
                                            uint64_t b_desc, uint32_t idesc,
                                            uint32_t enable_d) {
    asm volatile(
        "{\n\t"
        ".reg .pred p;\n\t"
        "setp.ne.u32 p, %5, 0;\n\t"
        "tcgen05.mma.cta_group::1.kind::tf32 [%0], [%1], %2, %3, {%4, %4, %4, %4}, p;\n\t"
        "}"
        :: "r"(d_tmem), "r"(a_tmem), "l"(b_desc), "r"(idesc), "r"(0u), "r"(enable_d)
        : "memory");
}

// K-major SW128 descriptor (version=1, SBO=64, LBO=1)
__device__ __forceinline__ uint64_t make_desc(uint32_t addr) {
    const uint64_t BASE = (2ull << 61) | (1ull << 46) | (64ull << 32) | (1ull << 16);
    return BASE | ((uint64_t)(addr >> 4) & 0x3FFFull);
}

// blocked-atom SW128 layout for a 128-row x 512-byte tile:
// atom = 8 rows x 128 bytes, 16 atom-rows x 4 atom-cols, atom_off = arow + acol*16
__device__ __forceinline__ uint32_t swz_off(uint32_t row, uint32_t cbyte) {
    uint32_t off = ((row >> 3) + (cbyte >> 7) * 16u) * 1024u
                 + (row & 7u) * 128u + (cbyte & 127u);
    return off ^ ((off >> 3) & 0x70u);
}
#endif  // !RWF_NO_TCGEN05

// ---------------------------------------------------------------------------
// Kernel
// ---------------------------------------------------------------------------
__global__ void __launch_bounds__(NTHREADS, 1)
rwf_tf32_kernel(const float* __restrict__ x, const float* __restrict__ s,
                const float* __restrict__ V, const float* __restrict__ bias,
                float* __restrict__ out, int n_tiles)
{
    extern __shared__ char smem_raw[];

#ifdef RWF_NO_TCGEN05
    // =======================================================================
    // Portable fallback (compute_103 PTX stage): smem-tiled FFMA GEMM.
    // =======================================================================
    float* ws     = (float*)smem_raw;          // [128][129] W' = exp(s)*V
    float* xs     = ws + 128 * 129;            // [128][129] x tile
    float* bias_s = xs + 128 * 129;
    float* sexp_s = bias_s + 128;

    const int tid = threadIdx.x;
    if (tid < 128) {
        sexp_s[tid] = expf(s[tid]);
        bias_s[tid] = bias[tid];
    }
    __syncthreads();
    for (int idx = tid; idx < 128 * 128; idx += NTHREADS) {
        int k = idx >> 7, n = idx & 127;
        ws[k * 129 + n] = sexp_s[k] * V[idx];
    }
    __syncthreads();

    for (int tile = blockIdx.x; tile < n_tiles; tile += gridDim.x) {
        const float* src = x + (size_t)tile * 16384;
        for (int idx = tid; idx < 16384; idx += NTHREADS) {
            int r = idx >> 7, k = idx & 127;
            xs[r * 129 + k] = src[idx];
        }
        __syncthreads();
        if (tid < 256) {
            const int row = tid & 127;
            const int n0  = (tid >> 7) * 64;
            float acc[64];
#pragma unroll
            for (int n = 0; n < 64; n++) acc[n] = bias_s[n0 + n];
            for (int k = 0; k < 128; k++) {
                float xv = xs[row * 129 + k];
#pragma unroll
                for (int n = 0; n < 64; n++)
                    acc[n] = fmaf(xv, ws[k * 129 + n0 + n], acc[n]);
            }
            float* dst = out + ((size_t)tile * 128 + row) * 128 + n0;
#pragma unroll
            for (int n = 0; n < 64; n++) dst[n] = tanh_fast(acc[n]);
        }
        __syncthreads();
    }
#else
    // =======================================================================
    // sm_103a path: TS-mode tcgen05 TF32, 3-deep ring, dedicated MMA warp.
    // =======================================================================
    const uint32_t smem0 = smem_u32(smem_raw);
    const uint32_t base  = (smem0 + 1023u) & ~1023u;
    char* gen = smem_raw + (base - smem0);

    float* bias_s = (float*)(gen + OFF_BIAS);
    float* sexp_s = (float*)(gen + OFF_SEXP);

    const int tid = threadIdx.x;
    const int wid = tid >> 5;
    const int lid = tid & 31;

    // ---- init (minimal critical path before fills start) ------------------
    if (wid == 12) TCG_ALLOC(base + MB_TMEM, 512);
    if (tid == 0) {
        MBAR_INIT(base + MB_AF + 0, 128);
        MBAR_INIT(base + MB_AF + 8, 128);
        MBAR_INIT(base + MB_AF + 16, 128);
        MBAR_INIT(base + MB_DF + 0, 1);
        MBAR_INIT(base + MB_DF + 8, 1);
        MBAR_INIT(base + MB_DF + 16, 1);
        MBAR_INIT(base + MB_DE + 0, 8);
        MBAR_INIT(base + MB_DE + 8, 8);
        MBAR_INIT(base + MB_DE + 16, 8);
        MBAR_INIT(base + MB_WF, 4);
    }
    __syncthreads();

    uint32_t tmem_base;
    asm volatile("ld.shared.b32 %0, [%1];" : "=r"(tmem_base) : "r"(base + MB_TMEM));

    const int grid = gridDim.x;
    const int bid  = blockIdx.x;

    if (wid >= 8 && wid < 12) {
        // -------- producers (warps 8-11): pure fill engines ---------------
        const int ptid = tid - 256;                 // 0..127
        const float4* __restrict__ x4 = (const float4*)x;
        const uint32_t cb = ((uint32_t)ptid & 31u) * 16u;
        int t = 0, r3 = 0, q3ph = 0;                // t%3, (t/3)&1
        int pr3 = 0;
        for (int tile = bid; tile < n_tiles; tile += grid, ++t) {
            if (t >= 3) {
                // slot r3 free once MMA(t-3) committed: same slot, prev phase
                MBAR_WAIT(base + MB_DF + 8 * r3, q3ph ^ 1);
            }
            const uint32_t abase = base + OFF_A0 + (uint32_t)r3 * A_STRIDE;
            const float4* src = x4 + (size_t)tile * 4096;
#pragma unroll
            for (int i = 0; i < 32; i++) {
                const int f = i * 128 + ptid;
                const uint32_t addr = abase + swz_off((uint32_t)f >> 5, cb);
                CP_ASYNC16(addr, src + f);
            }
            CP_COMMIT();
            if (t > 0) {
                CP_WAIT1();                         // fill(t-1) complete
                FENCE_ASYNC_SHARED();
                MBAR_ARRIVE(base + MB_AF + 8 * pr3);
            }
            pr3 = r3;
            if (++r3 == 3) { r3 = 0; q3ph ^= 1; }
        }
        if (t > 0) {                                // tail: last fill
            CP_WAIT0();
            FENCE_ASYNC_SHARED();
            MBAR_ARRIVE(base + MB_AF + 8 * pr3);
        }
    } else if (wid == 12) {
        // -------- dedicated MMA warp ---------------------------------------
        MBAR_WAIT(base + MB_WF, 0);                 // W resident in TMEM
        TCG_FENCE_AFTER();
        int u = 0, r3 = 0, ph = 0;                  // u%3, (u/3)&1
        for (int tile = bid; tile < n_tiles; tile += grid, ++u) {
            MBAR_WAIT(base + MB_AF + 8 * r3, ph);               // B ready
            if (u >= 3)
                MBAR_WAIT(base + MB_DE + 8 * r3, ph ^ 1);       // D drained
            TCG_FENCE_AFTER();
            if (elect_one()) {
                const uint32_t d = tmem_base + 128u * (uint32_t)r3;
                const uint64_t bd = make_desc(base + OFF_A0 + (uint32_t)r3 * A_STRIDE);
#pragma unroll
                for (int k = 0; k < 16; k++) {
                    const uint64_t koff = (uint64_t)((k >> 2) * 1024 + (k & 3) * 2);
                    mma_tf32_ts(d, tmem_base + TM_W + k * 8, bd + koff,
                                IDESC_TF32, (k > 0) ? 1u : 0u);
                }
                TCG_COMMIT(base + MB_DF + 8 * r3);
            }
            if (++r3 == 3) { r3 = 0; ph ^= 1; }
        }
    } else {
        // -------- epilogue (warps 0-7): W build, then direct stores --------
        // W build overlapped with the first fills (warps 0-3 write TMEM).
        if (tid < 128) {
            sexp_s[tid] = expf(s[tid]) * W_BIAS_COMP;
            bias_s[tid] = bias[tid];
        }
        asm volatile("bar.sync 3, 256;" ::: "memory");  // sexp/bias visible
        if (wid < 4) {
            const uint32_t woff = ((uint32_t)wid) << 21;  // subpartition
#pragma unroll
            for (int c = 0; c < 4; c++) {
                uint32_t wr[32];
#pragma unroll
                for (int kk = 0; kk < 32; kk++) {
                    const int k = c * 32 + kk;
                    float w = sexp_s[k] * V[(size_t)k * 128 + tid];
                    asm("cvt.rna.tf32.f32 %0, %1;" : "=r"(wr[kk]) : "f"(w));
                }
                TCG_ST_X32(tmem_base + TM_W + c * 32 + woff, wr);
            }
            TCG_WAIT_ST();
            TCG_FENCE_BEFORE();
            if (elect_one()) MBAR_ARRIVE(base + MB_WF);
        }
        // D transposed: lane = n (contiguous in out), TMEM col = m.
        const int sp   = wid & 3;        // TMEM subpartition (n block)
        const int half = wid >> 2;       // m half (0: rows 0-63, 1: 64-127)
        const int n    = sp * 32 + lid;  // this thread's output column
        const int mbase = half * 64;
        const float bn = bias_s[n];
        int t = 0, r3 = 0, q3ph = 0;
        for (int tile = bid; tile < n_tiles; tile += grid, ++t) {
            MBAR_WAIT(base + MB_DF + 8 * r3, q3ph);
            TCG_FENCE_AFTER();
            const uint32_t dt = tmem_base + 128u * (uint32_t)r3 + mbase;
            uint32_t ra[32], rb[32];
            TCG_LD_X32(ra, dt);
            TCG_LD_X32(rb, dt + 32);
            TCG_WAIT_LD();
            TCG_FENCE_BEFORE();
            // D buffer drained into registers -> release it immediately
            if (elect_one()) MBAR_ARRIVE(base + MB_DE + 8 * r3);
            // fully-coalesced streaming stores: 32 lanes x 4B contiguous
            float* dst = out + ((size_t)tile * 128 + (size_t)mbase) * 128 + n;
#pragma unroll
            for (int j = 0; j < 32; j++)
                __stcs(dst + (size_t)j * 128, tanh_fast(__uint_as_float(ra[j]) + bn));
#pragma unroll
            for (int j = 0; j < 32; j++)
                __stcs(dst + (size_t)(32 + j) * 128, tanh_fast(__uint_as_float(rb[j]) + bn));
            if (++r3 == 3) { r3 = 0; q3ph ^= 1; }
        }
    }

    // ---- teardown ---------------------------------------------------------
    __syncthreads();
    if (wid == 12) {
        TCG_RELINQ();
        TCG_DEALLOC(tmem_base, 512);
    }
#endif  // RWF_NO_TCGEN05
}

// ---------------------------------------------------------------------------
// Launch
// ---------------------------------------------------------------------------
extern "C" void kernel_launch(void* const* d_in, const int* in_sizes, int n_in,
                              void* d_out, int out_size)
{
    const float* x    = (const float*)d_in[0];
    const float* s    = (const float*)d_in[1];
    const float* V    = (const float*)d_in[2];
    const float* bias = (const float*)d_in[3];
    float* out = (float*)d_out;

    const long long M = (long long)in_sizes[0] / 128;   // rows of x
    const int n_tiles = (int)(M >> 7);                  // 128-row tiles (8192)

    cudaFuncSetAttribute(rwf_tf32_kernel,
                         cudaFuncAttributeMaxDynamicSharedMemorySize, SMEM_BYTES);

    int sms = 148;
    int dev = 0;
    cudaGetDevice(&dev);
    cudaDeviceGetAttribute(&sms, cudaDevAttrMultiProcessorCount, dev);
    int grid = (sms < n_tiles) ? sms : n_tiles;
    if (grid < 1) grid = 1;

    rwf_tf32_kernel<<<grid, NTHREADS, SMEM_BYTES>>>(x, s, V, bias, out, n_tiles);
}